// round 13
// baseline (speedup 1.0000x reference)
#include <cuda_runtime.h>
#include <math.h>

#define B_   32
#define W_   50
#define H_   192
#define H4   768
#define V_   32000
#define TD   49
#define ROWS 1568   // TD * B_

// ---------------- device scratch (zero-initialized at module load) ----------------
__device__ float g_xf[W_*B_*H4];        // enc fwd pre:  emb@Wf + bf   (t,b,n)
__device__ float g_xb[W_*B_*H4];        // enc bwd pre:  emb@Wb + bb   (t,b,n)
__device__ float g_xd[TD*B_*H4];        // dec pre:      demb@Wd1 + bd (t,b,n)
__device__ float g_outs_f[W_*B_*H_];
__device__ float g_outs_b[W_*B_*H_];
__device__ float g_enc_out[B_*W_*H_];   // (b,t,h)
__device__ float g_hfp[2][B_*H_];       // ping-pong h (fwd)
__device__ float g_hbp[2][B_*H_];       // ping-pong h (bwd)
__device__ float g_cf[B_*H_], g_cb[B_*H_];
__device__ float g_dh[2][B_*H_];        // decoder h ping-pong
__device__ float g_dc[B_*H_];
__device__ float g_hcat[1600*384];      // rows padded to 1600; [h(0:192)|c_t(192:384)]
__device__ float g_betas[TD*B_*W_];
__device__ float g_gate[TD*B_];
__device__ float g_rmax[ROWS], g_rsum[ROWS];

__device__ __forceinline__ float sigf(float x){ return 1.0f/(1.0f + expf(-x)); }

// ---------------- f32x2 packed FMA helpers (sm_100+) ----------------
__device__ __forceinline__ unsigned long long ffma2(unsigned long long a,
                                                    unsigned long long b,
                                                    unsigned long long c){
    unsigned long long d;
    asm("fma.rn.f32x2 %0, %1, %2, %3;" : "=l"(d) : "l"(a), "l"(b), "l"(c));
    return d;
}
__device__ __forceinline__ unsigned long long packdup(float x){
    unsigned long long d;
    asm("mov.b64 %0, {%1, %1};" : "=l"(d) : "f"(x));
    return d;
}
__device__ __forceinline__ float2 unpk(unsigned long long v){
    float lo, hi;
    asm("mov.b64 {%0, %1}, %2;" : "=f"(lo), "=f"(hi) : "l"(v));
    return make_float2(lo, hi);
}

// ---------------- init ----------------
__global__ void k_zero_state() {
    int i = blockIdx.x * 256 + threadIdx.x;
    if (i < B_*H_) {
        g_hfp[0][i] = 0.f; g_hfp[1][i] = 0.f;
        g_hbp[0][i] = 0.f; g_hbp[1][i] = 0.f;
        g_cf[i] = 0.f;     g_cb[i] = 0.f;
    }
}

// ---------------- pre-GEMM: gathered embeddings @ W (K=192) ----------------
// which: 0 -> g_xf, 1 -> g_xb, 2 -> g_xd.  rows = n_t*32, row = t*32+b.
__global__ void __launch_bounds__(256) k_pre_gemm(const int* __restrict__ tokens,
                                                  const float* __restrict__ emb,
                                                  const float* __restrict__ Wm,
                                                  const float* __restrict__ bias,
                                                  int which, int rows) {
    float* outp = (which == 0) ? g_xf : (which == 1) ? g_xb : g_xd;
    __shared__ float As[16][192];
    int row0 = blockIdx.x * 16;
    int col0 = blockIdx.y * 128;
    int tid = threadIdx.x;
    for (int i = tid; i < 16*192; i += 256) {
        int r = i / 192, k = i % 192;
        int row = row0 + r;
        float v = 0.f;
        if (row < rows) {
            int t = row >> 5, b = row & 31;
            int tok = tokens[b*W_ + t];
            v = emb[tok*H_ + k];
        }
        As[r][k] = v;
    }
    __syncthreads();
    int r0 = tid >> 5;
    int c  = col0 + (tid & 31);
    float a00=0.f,a01=0.f,a02=0.f,a03=0.f;
    float a10=0.f,a11=0.f,a12=0.f,a13=0.f;
    #pragma unroll 4
    for (int k = 0; k < H_; k++) {
        float b0 = Wm[k*H4 + c];
        float b1 = Wm[k*H4 + c + 32];
        float b2 = Wm[k*H4 + c + 64];
        float b3 = Wm[k*H4 + c + 96];
        float x0 = As[r0][k];
        float x1 = As[r0 + 8][k];
        a00 = fmaf(x0,b0,a00); a01 = fmaf(x0,b1,a01); a02 = fmaf(x0,b2,a02); a03 = fmaf(x0,b3,a03);
        a10 = fmaf(x1,b0,a10); a11 = fmaf(x1,b1,a11); a12 = fmaf(x1,b2,a12); a13 = fmaf(x1,b3,a13);
    }
    float bb0 = bias[c], bb1 = bias[c+32], bb2 = bias[c+64], bb3 = bias[c+96];
    int row = row0 + r0;
    if (row < rows) {
        float* o = outp + row*H4;
        o[c] = a00+bb0; o[c+32] = a01+bb1; o[c+64] = a02+bb2; o[c+96] = a03+bb3;
    }
    row = row0 + r0 + 8;
    if (row < rows) {
        float* o = outp + row*H4;
        o[c] = a10+bb0; o[c+32] = a11+bb1; o[c+64] = a12+bb2; o[c+96] = a13+bb3;
    }
}

// ---------------- encoder step (both directions). grid (6 jchunks, 8 bgroups, 2 dirs) ----------------
__global__ void __launch_bounds__(256) k_enc_step(const float* __restrict__ Uf,
                                                  const float* __restrict__ Ub, int s) {
    int dir = blockIdx.z;
    int t = dir ? (W_ - 1 - s) : s;
    const float* xpre = dir ? g_xb : g_xf;
    const float* U    = dir ? Ub   : Uf;
    float* hin  = dir ? g_hbp[s & 1]       : g_hfp[s & 1];
    float* hout = dir ? g_hbp[(s & 1) ^ 1] : g_hfp[(s & 1) ^ 1];
    float* c    = dir ? g_cb : g_cf;
    float* outs = dir ? g_outs_b : g_outs_f;

    int b0 = blockIdx.y * 4;
    int j0 = blockIdx.x * 32;
    __shared__ float hs[4][192];
    __shared__ float zs[4][4][32];
    int tid = threadIdx.x;
    for (int i = tid; i < 4*192; i += 256)
        hs[i/192][i%192] = hin[(b0 + i/192)*H_ + (i%192)];
    __syncthreads();

    #pragma unroll
    for (int rep = 0; rep < 2; rep++) {
        int o  = tid + rep*256;
        int bl = o >> 7;
        int gt = (o >> 5) & 3;
        int j  = o & 31;
        int n  = gt*H_ + j0 + j;
        float acc = xpre[(t*B_ + b0 + bl)*H4 + n];
        const float* uc = U + n;
        const float* hv = hs[bl];
        #pragma unroll 8
        for (int k = 0; k < H_; k++) acc = fmaf(hv[k], uc[k*H4], acc);
        zs[bl][gt][j] = acc;
    }
    __syncthreads();

    if (tid < 128) {
        int bl = tid >> 5, j = tid & 31;
        int b = b0 + bl, jj = j0 + j;
        float zi = zs[bl][0][j], zf = zs[bl][1][j], zg = zs[bl][2][j], zo = zs[bl][3][j];
        float cn = sigf(zf)*c[b*H_ + jj] + sigf(zi)*tanhf(zg);
        float hn = sigf(zo)*tanhf(cn);
        c[b*H_ + jj]    = cn;
        hout[b*H_ + jj] = hn;
        outs[(t*B_ + b)*H_ + jj] = hn;
    }
}

// ---------------- combine encoder outputs + initial decoder state ----------------
__global__ void k_enc_combine() {
    int i = blockIdx.x * 256 + threadIdx.x;
    if (i < B_*W_*H_) {
        int b = i / (W_*H_);
        int rem = i % (W_*H_);
        int t = rem / H_;
        int j = rem % H_;
        g_enc_out[i] = g_outs_f[(t*B_ + b)*H_ + j] + g_outs_b[(t*B_ + b)*H_ + j];
    }
    if (i < B_*H_) {
        // final fwd/bwd states live in slot 0 (s=49 writes (49&1)^1 = 0)
        g_dh[0][i] = g_hfp[0][i] + g_hbp[0][i];
        g_dc[i]    = g_cf[i] + g_cb[i];
    }
}

// ---------------- decoder attention: q, scores, softmax, betas/gate, c_t. grid = 32 (per b) ----------------
__global__ void __launch_bounds__(256) k_dec_attn(const float* __restrict__ Wq,
                                                  const float* __restrict__ sentinel,
                                                  const float* __restrict__ a_bias, int t) {
    int b = blockIdx.x;
    const float* hin = g_dh[t & 1];
    __shared__ float hsh[192];
    __shared__ float q[192];
    __shared__ float sc[51];
    int tid = threadIdx.x;
    if (tid < 192) hsh[tid] = hin[b*H_ + tid];
    __syncthreads();
    if (tid < 192) {
        float acc = 0.f;
        #pragma unroll 8
        for (int k = 0; k < H_; k++) acc = fmaf(hsh[k], Wq[k*H_ + tid], acc);
        q[tid] = acc;
    }
    __syncthreads();
    int warp = tid >> 5, lane = tid & 31;
    for (int j = warp; j < 51; j += 8) {
        const float* fr = (j < 50) ? (g_enc_out + (b*W_ + j)*H_) : sentinel;
        float s = 0.f;
        for (int k = lane; k < H_; k += 32) s += tanhf(fr[k] * q[k]);
        #pragma unroll
        for (int off = 16; off; off >>= 1) s += __shfl_xor_sync(0xffffffffu, s, off);
        if (lane == 0) sc[j] = s + a_bias[t*(W_+1) + j];
    }
    __syncthreads();
    if (tid < 32) {
        float v0 = (tid < 51) ? sc[tid] : -1e30f;
        float v1 = (tid + 32 < 51) ? sc[tid + 32] : -1e30f;
        float m = fmaxf(v0, v1);
        #pragma unroll
        for (int off = 16; off; off >>= 1) m = fmaxf(m, __shfl_xor_sync(0xffffffffu, m, off));
        float e0 = (tid < 51) ? expf(v0 - m) : 0.f;
        float e1 = (tid + 32 < 51) ? expf(v1 - m) : 0.f;
        float s = e0 + e1;
        #pragma unroll
        for (int off = 16; off; off >>= 1) s += __shfl_xor_sync(0xffffffffu, s, off);
        float inv = 1.f / s;
        if (tid < 51) sc[tid] = e0 * inv;
        if (tid + 32 < 51) sc[tid + 32] = e1 * inv;
    }
    __syncthreads();
    if (tid < 50) g_betas[(t*B_ + b)*W_ + tid] = sc[tid];
    if (tid == 50) g_gate[t*B_ + b] = sc[50];
    if (tid < 192) {
        float acc = 0.f;
        #pragma unroll
        for (int w = 0; w < W_; w++)
            acc = fmaf(g_enc_out[(b*W_ + w)*H_ + tid], sc[w], acc);
        g_hcat[(t*B_ + b)*384 + 192 + tid] = acc;
    }
}

// ---------------- decoder LSTM cell. grid (6 jchunks, 8 bgroups) ----------------
__global__ void __launch_bounds__(256) k_dec_cell(const float* __restrict__ Ud,
                                                  const float* __restrict__ Wd, int t) {
    const float* hin = g_dh[t & 1];
    float* hout      = g_dh[(t & 1) ^ 1];
    int b0 = blockIdx.y * 4, j0 = blockIdx.x * 32;
    __shared__ float hs[4][192], cts[4][192];
    __shared__ float zs[4][4][32];
    int tid = threadIdx.x;
    for (int i = tid; i < 4*192; i += 256) {
        int bl = i/192, k = i%192;
        hs[bl][k]  = hin[(b0 + bl)*H_ + k];
        cts[bl][k] = g_hcat[(t*B_ + b0 + bl)*384 + 192 + k];
    }
    __syncthreads();
    const float* Wd2 = Wd + 192*H4;
    #pragma unroll
    for (int rep = 0; rep < 2; rep++) {
        int o  = tid + rep*256;
        int bl = o >> 7, gt = (o >> 5) & 3, j = o & 31;
        int n  = gt*H_ + j0 + j;
        float acc = g_xd[(t*B_ + b0 + bl)*H4 + n];
        const float* uc = Ud + n;
        const float* wc = Wd2 + n;
        #pragma unroll 8
        for (int k = 0; k < H_; k++) acc = fmaf(hs[bl][k], uc[k*H4], acc);
        #pragma unroll 8
        for (int k = 0; k < H_; k++) acc = fmaf(cts[bl][k], wc[k*H4], acc);
        zs[bl][gt][j] = acc;
    }
    __syncthreads();
    if (tid < 128) {
        int bl = tid >> 5, j = tid & 31;
        int b = b0 + bl, jj = j0 + j;
        float zi = zs[bl][0][j], zf = zs[bl][1][j], zg = zs[bl][2][j], zo = zs[bl][3][j];
        float cn = sigf(zf)*g_dc[b*H_ + jj] + sigf(zi)*tanhf(zg);
        float hn = sigf(zo)*tanhf(cn);
        g_dc[b*H_ + jj] = cn;
        hout[b*H_ + jj] = hn;
        g_hcat[(t*B_ + b)*384 + jj] = hn;
    }
}

// ---------------- big GEMM: logits = hcat[1568x384] @ Wdense[384x32000] + bdense ----------------
// BM=64, BN=128, BK=16, 256 threads, 8x4 micro-tile via fma.rn.f32x2 (row-pairs).
__global__ void __launch_bounds__(256) k_dense_gemm(const float* __restrict__ Wdense,
                                                    const float* __restrict__ bdense,
                                                    float* __restrict__ out) {
    __shared__ float As[16][68];   // [k][m], padded row (272B -> 16B aligned)
    __shared__ float Bs[16][128];
    int m0 = blockIdx.y * 64;
    int n0 = blockIdx.x * 128;
    int tid = threadIdx.x;
    int ty = tid >> 5, tx = tid & 31;

    unsigned long long accp[4][4];
    #pragma unroll
    for (int i = 0; i < 4; i++)
        #pragma unroll
        for (int j = 0; j < 4; j++) accp[i][j] = 0ULL;

    for (int k0 = 0; k0 < 384; k0 += 16) {
        {
            int m  = tid >> 2;
            int kc = (tid & 3) * 4;
            float4 a4 = *(const float4*)(g_hcat + (m0 + m)*384 + k0 + kc);
            As[kc+0][m] = a4.x; As[kc+1][m] = a4.y; As[kc+2][m] = a4.z; As[kc+3][m] = a4.w;
        }
        #pragma unroll
        for (int l = 0; l < 2; l++) {
            int idx = tid + l*256;
            int r = idx >> 5, c4 = idx & 31;
            *(float4*)(&Bs[r][c4*4]) = *(const float4*)(Wdense + (size_t)(k0 + r)*V_ + n0 + c4*4);
        }
        __syncthreads();
        #pragma unroll
        for (int kk = 0; kk < 16; kk++) {
            ulonglong2 a01 = *(const ulonglong2*)(&As[kk][ty*8]);
            ulonglong2 a23 = *(const ulonglong2*)(&As[kk][ty*8 + 4]);
            float4 bv = *(const float4*)(&Bs[kk][tx*4]);
            unsigned long long bp0 = packdup(bv.x);
            unsigned long long bp1 = packdup(bv.y);
            unsigned long long bp2 = packdup(bv.z);
            unsigned long long bp3 = packdup(bv.w);
            unsigned long long ap[4] = {a01.x, a01.y, a23.x, a23.y};
            #pragma unroll
            for (int rp = 0; rp < 4; rp++) {
                accp[rp][0] = ffma2(ap[rp], bp0, accp[rp][0]);
                accp[rp][1] = ffma2(ap[rp], bp1, accp[rp][1]);
                accp[rp][2] = ffma2(ap[rp], bp2, accp[rp][2]);
                accp[rp][3] = ffma2(ap[rp], bp3, accp[rp][3]);
            }
        }
        __syncthreads();
    }
    float4 bias4 = *(const float4*)(bdense + n0 + tx*4);
    #pragma unroll
    for (int rp = 0; rp < 4; rp++) {
        float2 c0 = unpk(accp[rp][0]);
        float2 c1 = unpk(accp[rp][1]);
        float2 c2 = unpk(accp[rp][2]);
        float2 c3 = unpk(accp[rp][3]);
        #pragma unroll
        for (int sel = 0; sel < 2; sel++) {
            int m = m0 + ty*8 + rp*2 + sel;
            if (m < ROWS) {
                int t = m >> 5, b = m & 31;
                float4 o4;
                o4.x = (sel ? c0.y : c0.x) + bias4.x;
                o4.y = (sel ? c1.y : c1.x) + bias4.y;
                o4.z = (sel ? c2.y : c2.x) + bias4.z;
                o4.w = (sel ? c3.y : c3.x) + bias4.w;
                *(float4*)(out + (size_t)(b*TD + t)*V_ + n0 + tx*4) = o4;
            }
        }
    }
}

// ---------------- softmax stats (online max/sum). grid = 1568 rows ----------------
__global__ void __launch_bounds__(256) k_softmax_stats(const float* __restrict__ out) {
    int r = blockIdx.x;            // r = t*32 + b
    int t = r >> 5, b = r & 31;
    const float* row = out + (size_t)(b*TD + t)*V_;
    int tid = threadIdx.x;
    float m = -1e30f, s = 0.f;
    for (int v = tid*4; v < V_; v += 1024) {
        float4 x4 = *(const float4*)(row + v);
        float xs[4] = {x4.x, x4.y, x4.z, x4.w};
        #pragma unroll
        for (int i = 0; i < 4; i++) {
            float x = xs[i];
            if (x > m) { s = s*expf(m - x) + 1.f; m = x; }
            else       { s += expf(x - m); }
        }
    }
    __shared__ float sm[256], ss[256];
    sm[tid] = m; ss[tid] = s;
    __syncthreads();
    for (int off = 128; off; off >>= 1) {
        if (tid < off) {
            float m2 = sm[tid + off], s2 = ss[tid + off];
            float M = fmaxf(sm[tid], m2);
            ss[tid] = ss[tid]*expf(sm[tid] - M) + s2*expf(m2 - M);
            sm[tid] = M;
        }
        __syncthreads();
    }
    if (tid == 0) { g_rmax[r] = sm[0]; g_rsum[r] = ss[0]; }
}

// ---------------- normalize: out = g * softmax(logits) ----------------
__global__ void __launch_bounds__(256) k_normalize(float* __restrict__ out) {
    int idx = blockIdx.x * 256 + threadIdx.x;    // float4 index
    if (idx >= ROWS * (V_/4)) return;
    int ro = idx / (V_/4);                       // ro = b*49 + t
    int b = ro / TD, t = ro % TD;
    int r = t*B_ + b;
    float m  = g_rmax[r];
    float inv = 1.f / g_rsum[r];
    float g  = g_gate[r];
    float4 x = ((float4*)out)[idx];
    x.x = g * expf(x.x - m) * inv;
    x.y = g * expf(x.y - m) * inv;
    x.z = g * expf(x.z - m) * inv;
    x.w = g * expf(x.w - m) * inv;
    ((float4*)out)[idx] = x;
}

// ---------------- pointer scatter: out += (1-g) * beta at encoder tokens ----------------
__global__ void k_scatter(const int* __restrict__ enc_in, float* __restrict__ out) {
    int i = blockIdx.x * 256 + threadIdx.x;
    if (i >= TD*B_*W_) return;
    int w  = i % W_;
    int rb = i / W_;                 // t*32 + b
    int b = rb & 31, t = rb >> 5;
    float g = g_gate[rb];
    float beta = g_betas[rb*W_ + w];
    int tok = enc_in[b*W_ + w];
    atomicAdd(out + (size_t)(b*TD + t)*V_ + tok, (1.f - g) * beta);
}

// ---------------- launch ----------------
extern "C" void kernel_launch(void* const* d_in, const int* in_sizes, int n_in,
                              void* d_out, int out_size) {
    const int*   enc_in  = (const int*)d_in[0];
    const int*   dec_in  = (const int*)d_in[1];
    const float* emb     = (const float*)d_in[2];
    const float* Wf      = (const float*)d_in[3];
    const float* Uf      = (const float*)d_in[4];
    const float* bf      = (const float*)d_in[5];
    const float* Wb      = (const float*)d_in[6];
    const float* Ub      = (const float*)d_in[7];
    const float* bb      = (const float*)d_in[8];
    const float* Wd      = (const float*)d_in[9];
    const float* Ud      = (const float*)d_in[10];
    const float* bd      = (const float*)d_in[11];
    const float* Wq      = (const float*)d_in[12];
    const float* Wdense  = (const float*)d_in[13];
    const float* bdense  = (const float*)d_in[14];
    const float* sentinel= (const float*)d_in[15];
    const float* a_bias  = (const float*)d_in[16];
    float* out = (float*)d_out;

    k_zero_state<<<24, 256>>>();

    dim3 gpe((W_*B_ + 15)/16, 6);
    k_pre_gemm<<<gpe, 256>>>(enc_in, emb, Wf, bf, 0, W_*B_);
    k_pre_gemm<<<gpe, 256>>>(enc_in, emb, Wb, bb, 1, W_*B_);
    dim3 gpd((TD*B_ + 15)/16, 6);
    k_pre_gemm<<<gpd, 256>>>(dec_in, emb, Wd, bd, 2, TD*B_);

    for (int s = 0; s < W_; s++)
        k_enc_step<<<dim3(6, 8, 2), 256>>>(Uf, Ub, s);

    k_enc_combine<<<(B_*W_*H_ + 255)/256, 256>>>();

    for (int t = 0; t < TD; t++) {
        k_dec_attn<<<B_, 256>>>(Wq, sentinel, a_bias, t);
        k_dec_cell<<<dim3(6, 8), 256>>>(Ud, Wd, t);
    }

    k_dense_gemm<<<dim3(V_/128, (ROWS + 63)/64), 256>>>(Wdense, bdense, out);
    k_softmax_stats<<<ROWS, 256>>>(out);
    k_normalize<<<(ROWS*(V_/4) + 255)/256, 256>>>(out);
    k_scatter<<<(TD*B_*W_ + 255)/256, 256>>>(enc_in, out);
}

// round 14
// speedup vs baseline: 1.4390x; 1.4390x over previous
#include <cuda_runtime.h>
#include <math.h>

#define B_   32
#define W_   50
#define H_   192
#define H4   768
#define V_   32000
#define TD   49
#define ROWS 1568   // TD * B_

// ---------------- device scratch (zero-initialized at module load) ----------------
__device__ float g_xf[1600*H4];         // enc fwd pre:  emb@Wf + bf   (t*32+b, n)
__device__ float g_xb[1600*H4];         // enc bwd pre
__device__ float g_xd[ROWS*H4];         // dec pre:      demb@Wd[0:192] + bd
__device__ float g_outs_f[W_*B_*H_];
__device__ float g_outs_b[W_*B_*H_];
__device__ float g_hfp[2][B_*H_];       // ping-pong h (fwd)
__device__ float g_hbp[2][B_*H_];       // ping-pong h (bwd)
__device__ float g_cf[B_*H_], g_cb[B_*H_];
__device__ float g_dh[2][B_*H_];        // decoder h ping-pong
__device__ float g_hcat[1600*384];      // rows padded to 1600; [h(0:192)|c_t(192:384)]
__device__ float g_betas[TD*B_*W_];
__device__ float g_gate[TD*B_];
__device__ int   g_cnt[512];            // grid-sync counters

__device__ __forceinline__ float sigf(float x){ return 1.0f/(1.0f + expf(-x)); }

// ---------------- grid sync (global counter; CTAs guaranteed co-resident) ----------------
__device__ __forceinline__ void grid_sync(int idx, int n) {
    __syncthreads();
    if (threadIdx.x == 0) {
        __threadfence();
        atomicAdd(&g_cnt[idx], 1);
        while (*((volatile int*)&g_cnt[idx]) < n) __nanosleep(32);
        __threadfence();
    }
    __syncthreads();
}

// ---------------- f32x2 packed FMA helpers (sm_100+) ----------------
__device__ __forceinline__ unsigned long long ffma2(unsigned long long a,
                                                    unsigned long long b,
                                                    unsigned long long c){
    unsigned long long d;
    asm("fma.rn.f32x2 %0, %1, %2, %3;" : "=l"(d) : "l"(a), "l"(b), "l"(c));
    return d;
}
__device__ __forceinline__ unsigned long long packdup(float x){
    unsigned long long d;
    asm("mov.b64 %0, {%1, %1};" : "=l"(d) : "f"(x));
    return d;
}
__device__ __forceinline__ float2 unpk(unsigned long long v){
    float lo, hi;
    asm("mov.b64 {%0, %1}, %2;" : "=f"(lo), "=f"(hi) : "l"(v));
    return make_float2(lo, hi);
}

// ---------------- init ----------------
__global__ void k_zero_state() {
    int i = blockIdx.x * 256 + threadIdx.x;
    if (i < B_*H_) {
        g_hfp[0][i] = 0.f; g_hfp[1][i] = 0.f;
        g_hbp[0][i] = 0.f; g_hbp[1][i] = 0.f;
    }
    if (i < 512) g_cnt[i] = 0;
}

// ---------------- fused pre-GEMM: [enc@Wf | enc@Wb | dec@Wd_top] ----------------
// 4768 rows total; seg0 rows 0..1599 -> g_xf, seg1 -> g_xb, seg2 (1568 rows) -> g_xd.
__global__ void __launch_bounds__(256) k_pre(const int* __restrict__ enc_in,
                                             const int* __restrict__ dec_in,
                                             const float* __restrict__ emb,
                                             const float* __restrict__ Wf, const float* __restrict__ bfv,
                                             const float* __restrict__ Wb, const float* __restrict__ bbv,
                                             const float* __restrict__ Wd, const float* __restrict__ bdv) {
    __shared__ float As[192*16];   // [k][r]
    __shared__ float Bs[16*128];   // [r][c]
    int row0 = blockIdx.x * 16;
    int which = (row0 < 1600) ? 0 : (row0 < 3200) ? 1 : 2;
    const int*   toks = (which == 2) ? dec_in : enc_in;
    const float* Wm   = (which == 0) ? Wf : (which == 1) ? Wb : Wd;
    const float* bias = (which == 0) ? bfv : (which == 1) ? bbv : bdv;
    float* outp = (which == 0) ? g_xf : (which == 1) ? g_xb : g_xd;
    int lr0  = row0 - which * 1600;
    int col0 = blockIdx.y * 128;
    int tid = threadIdx.x;

    for (int i = tid; i < 16*192; i += 256) {
        int r = i / 192, k = i % 192;
        int lr = lr0 + r;
        int tok = toks[(lr & 31) * W_ + (lr >> 5)];
        As[k*16 + r] = emb[tok*H_ + k];
    }
    int tx = tid & 31, ty = tid >> 5;
    float a0c[4] = {0,0,0,0}, a1c[4] = {0,0,0,0};
    for (int k0 = 0; k0 < 192; k0 += 16) {
        __syncthreads();
        for (int i = tid; i < 16*128; i += 256) {
            int r = i >> 7, c = i & 127;
            Bs[i] = Wm[(size_t)(k0 + r)*H4 + col0 + c];
        }
        __syncthreads();
        #pragma unroll
        for (int kk = 0; kk < 16; kk++) {
            float a0 = As[(k0+kk)*16 + ty];
            float a1 = As[(k0+kk)*16 + ty + 8];
            float4 w = *(float4*)&Bs[kk*128 + tx*4];
            a0c[0] = fmaf(a0,w.x,a0c[0]); a0c[1] = fmaf(a0,w.y,a0c[1]);
            a0c[2] = fmaf(a0,w.z,a0c[2]); a0c[3] = fmaf(a0,w.w,a0c[3]);
            a1c[0] = fmaf(a1,w.x,a1c[0]); a1c[1] = fmaf(a1,w.y,a1c[1]);
            a1c[2] = fmaf(a1,w.z,a1c[2]); a1c[3] = fmaf(a1,w.w,a1c[3]);
        }
    }
    float4 b4 = *(const float4*)(bias + col0 + tx*4);
    float4 o;
    o.x = a0c[0]+b4.x; o.y = a0c[1]+b4.y; o.z = a0c[2]+b4.z; o.w = a0c[3]+b4.w;
    *(float4*)(outp + (size_t)(lr0 + ty)*H4 + col0 + tx*4) = o;
    o.x = a1c[0]+b4.x; o.y = a1c[1]+b4.y; o.z = a1c[2]+b4.z; o.w = a1c[3]+b4.w;
    *(float4*)(outp + (size_t)(lr0 + ty + 8)*H4 + col0 + tx*4) = o;
}

// ---------------- persistent encoder: 48 CTAs (24/dir), weight-stationary ----------------
__global__ void __launch_bounds__(256) k_encoder(const float* __restrict__ Uf,
                                                 const float* __restrict__ Ub) {
    extern __shared__ float esm[];
    float* ws = esm;           // 192 * 32  (U slice: [k][g*8+j])
    float* hs = esm + 6144;    // 192 * 33  (h transposed [k][b], pad 33)

    int cta = blockIdx.x;
    int dir = cta / 24;
    int nc  = cta % 24;
    const float* U    = dir ? Ub   : Uf;
    const float* xpre = dir ? g_xb : g_xf;
    float* outs = dir ? g_outs_b : g_outs_f;
    float* cfin = dir ? g_cb : g_cf;
    float* hping[2];
    hping[0] = dir ? g_hbp[0] : g_hfp[0];
    hping[1] = dir ? g_hbp[1] : g_hfp[1];

    int tid = threadIdx.x;
    int jl  = tid >> 5;        // 0..7
    int b   = tid & 31;
    int jg  = nc*8 + jl;       // 0..191

    // stage weight slice once: cols n = g*192 + nc*8 + j  -> ws[k*32 + g*8 + j]
    for (int i = tid; i < 192*32; i += 256) {
        int k = i >> 5, col = i & 31;
        int g = col >> 3, j = col & 7;
        ws[i] = U[k*H4 + g*H_ + nc*8 + j];
    }

    float c_reg = 0.f;
    for (int s = 0; s < W_; s++) {
        int t = dir ? (W_ - 1 - s) : s;
        const float* hin = hping[s & 1];
        // stage h transposed (L1-bypass: written by other CTAs)
        for (int i = tid; i < 192*32; i += 256) {
            int bb = i / 192, k = i % 192;
            hs[k*33 + bb] = __ldcg(&hin[i]);
        }
        __syncthreads();   // also orders ws on first iteration

        const float* xr = xpre + (size_t)(t*B_ + b)*H4;
        float acc0 = xr[0*H_ + jg];
        float acc1 = xr[1*H_ + jg];
        float acc2 = xr[2*H_ + jg];
        float acc3 = xr[3*H_ + jg];
        #pragma unroll 8
        for (int k = 0; k < H_; k++) {
            float hv = hs[k*33 + b];
            acc0 = fmaf(hv, ws[k*32 +      jl], acc0);
            acc1 = fmaf(hv, ws[k*32 +  8 + jl], acc1);
            acc2 = fmaf(hv, ws[k*32 + 16 + jl], acc2);
            acc3 = fmaf(hv, ws[k*32 + 24 + jl], acc3);
        }
        float cn = sigf(acc1)*c_reg + sigf(acc0)*tanhf(acc2);
        float hn = sigf(acc3)*tanhf(cn);
        c_reg = cn;
        hping[(s & 1) ^ 1][b*H_ + jg] = hn;
        outs[(t*B_ + b)*H_ + jg] = hn;

        if (s < W_ - 1) grid_sync(dir*64 + s, 24);
    }
    cfin[b*H_ + jg] = c_reg;
}

// ---------------- persistent decoder: 32 CTAs ----------------
// Per step: phase A (attn, CTA=batch), grid sync, phase B (cell, CTA=j-chunk of 6).
__global__ void __launch_bounds__(256) k_decoder(const float* __restrict__ Wq,
                                                 const float* __restrict__ sentinel,
                                                 const float* __restrict__ a_bias,
                                                 const float* __restrict__ Ud,
                                                 const float* __restrict__ Wd) {
    extern __shared__ float dsm[];
    float* fatt = dsm;                  // 51*192 = 9792 (attention memory for batch=cta)
    float* ws   = dsm + 9792;           // 384*24 = 9216 (Ud/Wd2 slice [k][g*6+j])
    float* hct  = dsm + 19008;          // 384*33 = 12672 ([h|ct] transposed, pad 33)
    __shared__ float hsh[192];
    __shared__ float q[192];
    __shared__ float sc[64];

    int cta = blockIdx.x;      // attn batch = cta; cell j-range = [cta*6, cta*6+6)
    int tid = threadIdx.x;

    // init: attention memory (enc_out for this batch) + sentinel row
    for (int i = tid; i < W_*H_; i += 256) {
        int w = i / H_, k = i % H_;
        fatt[i] = g_outs_f[(w*B_ + cta)*H_ + k] + g_outs_b[(w*B_ + cta)*H_ + k];
    }
    if (tid < H_) fatt[W_*H_ + tid] = sentinel[tid];

    // weight slice: cols n = g*192 + cta*6 + j, rows k<192 from Ud, k in [192,384) from Wd
    for (int i = tid; i < 384*24; i += 256) {
        int k = i / 24, col = i % 24;
        int g = col / 6, j = col % 6;
        int n = g*H_ + cta*6 + j;
        ws[i] = (k < 192) ? Ud[k*H4 + n] : Wd[(size_t)k*H4 + n];
    }

    // initial decoder state
    if (tid < H_)
        g_dh[0][cta*H_ + tid] = g_hfp[0][cta*H_ + tid] + g_hbp[0][cta*H_ + tid];
    int jl = tid >> 5;         // cell: 0..7, valid <6
    int b  = tid & 31;
    int jg = cta*6 + jl;
    float c_reg = 0.f;
    if (jl < 6) c_reg = g_cf[b*H_ + jg] + g_cb[b*H_ + jg];

    grid_sync(128, 32);

    for (int t = 0; t < TD; t++) {
        const float* hin = g_dh[t & 1];

        // ---- attn (batch = cta) ----
        if (tid < H_) hsh[tid] = __ldcg(&hin[cta*H_ + tid]);
        __syncthreads();
        if (tid < H_) {
            float a = 0.f;
            #pragma unroll 8
            for (int k = 0; k < H_; k++) a = fmaf(hsh[k], Wq[k*H_ + tid], a);
            q[tid] = a;
        }
        __syncthreads();
        int warp = tid >> 5, lane = tid & 31;
        for (int j = warp; j < 51; j += 8) {
            float s = 0.f;
            for (int k = lane; k < H_; k += 32) s += tanhf(fatt[j*H_ + k] * q[k]);
            #pragma unroll
            for (int off = 16; off; off >>= 1) s += __shfl_xor_sync(0xffffffffu, s, off);
            if (lane == 0) sc[j] = s + a_bias[t*(W_+1) + j];
        }
        __syncthreads();
        if (tid < 32) {
            float v0 = sc[tid];
            float v1 = (tid + 32 < 51) ? sc[tid + 32] : -1e30f;
            float m = fmaxf(v0, v1);
            #pragma unroll
            for (int off = 16; off; off >>= 1) m = fmaxf(m, __shfl_xor_sync(0xffffffffu, m, off));
            float e0 = expf(v0 - m);
            float e1 = (tid + 32 < 51) ? expf(v1 - m) : 0.f;
            float s = e0 + e1;
            #pragma unroll
            for (int off = 16; off; off >>= 1) s += __shfl_xor_sync(0xffffffffu, s, off);
            float inv = 1.f / s;
            sc[tid] = e0 * inv;
            if (tid + 32 < 51) sc[tid + 32] = e1 * inv;
        }
        __syncthreads();
        if (tid < W_) g_betas[(t*B_ + cta)*W_ + tid] = sc[tid];
        if (tid == W_) g_gate[t*B_ + cta] = sc[W_];
        if (tid < H_) {
            float a = 0.f;
            #pragma unroll
            for (int w = 0; w < W_; w++) a = fmaf(fatt[w*H_ + tid], sc[w], a);
            g_hcat[(size_t)(t*B_ + cta)*384 + 192 + tid] = a;
        }
        grid_sync(130 + 2*t, 32);

        // ---- cell (j-chunk = cta) ----
        for (int i = tid; i < 192*32; i += 256) {
            int bb = i / 192, k = i % 192;
            hct[k*33 + bb]         = __ldcg(&hin[i]);
            hct[(192 + k)*33 + bb] = __ldcg(&g_hcat[(size_t)(t*B_ + bb)*384 + 192 + k]);
        }
        __syncthreads();
        if (jl < 6) {
            const float* xr = g_xd + (size_t)(t*B_ + b)*H4;
            float acc0 = xr[0*H_ + jg];
            float acc1 = xr[1*H_ + jg];
            float acc2 = xr[2*H_ + jg];
            float acc3 = xr[3*H_ + jg];
            #pragma unroll 8
            for (int k = 0; k < 384; k++) {
                float hv = hct[k*33 + b];
                acc0 = fmaf(hv, ws[k*24 +      jl], acc0);
                acc1 = fmaf(hv, ws[k*24 +  6 + jl], acc1);
                acc2 = fmaf(hv, ws[k*24 + 12 + jl], acc2);
                acc3 = fmaf(hv, ws[k*24 + 18 + jl], acc3);
            }
            float cn = sigf(acc1)*c_reg + sigf(acc0)*tanhf(acc2);
            float hn = sigf(acc3)*tanhf(cn);
            c_reg = cn;
            g_dh[(t & 1) ^ 1][b*H_ + jg] = hn;
            g_hcat[(size_t)(t*B_ + b)*384 + jg] = hn;
        }
        if (t < TD - 1) grid_sync(131 + 2*t, 32);
    }
}

// ---------------- big GEMM: logits = hcat[1568x384] @ Wdense[384x32000] + bdense ----------------
__global__ void __launch_bounds__(256) k_dense_gemm(const float* __restrict__ Wdense,
                                                    const float* __restrict__ bdense,
                                                    float* __restrict__ out) {
    __shared__ float As[16][68];
    __shared__ float Bs[16][128];
    int m0 = blockIdx.y * 64;
    int n0 = blockIdx.x * 128;
    int tid = threadIdx.x;
    int ty = tid >> 5, tx = tid & 31;

    unsigned long long accp[4][4];
    #pragma unroll
    for (int i = 0; i < 4; i++)
        #pragma unroll
        for (int j = 0; j < 4; j++) accp[i][j] = 0ULL;

    for (int k0 = 0; k0 < 384; k0 += 16) {
        {
            int m  = tid >> 2;
            int kc = (tid & 3) * 4;
            float4 a4 = *(const float4*)(g_hcat + (size_t)(m0 + m)*384 + k0 + kc);
            As[kc+0][m] = a4.x; As[kc+1][m] = a4.y; As[kc+2][m] = a4.z; As[kc+3][m] = a4.w;
        }
        #pragma unroll
        for (int l = 0; l < 2; l++) {
            int idx = tid + l*256;
            int r = idx >> 5, c4 = idx & 31;
            *(float4*)(&Bs[r][c4*4]) = *(const float4*)(Wdense + (size_t)(k0 + r)*V_ + n0 + c4*4);
        }
        __syncthreads();
        #pragma unroll
        for (int kk = 0; kk < 16; kk++) {
            ulonglong2 a01 = *(const ulonglong2*)(&As[kk][ty*8]);
            ulonglong2 a23 = *(const ulonglong2*)(&As[kk][ty*8 + 4]);
            float4 bv = *(const float4*)(&Bs[kk][tx*4]);
            unsigned long long bp0 = packdup(bv.x);
            unsigned long long bp1 = packdup(bv.y);
            unsigned long long bp2 = packdup(bv.z);
            unsigned long long bp3 = packdup(bv.w);
            unsigned long long ap[4] = {a01.x, a01.y, a23.x, a23.y};
            #pragma unroll
            for (int rp = 0; rp < 4; rp++) {
                accp[rp][0] = ffma2(ap[rp], bp0, accp[rp][0]);
                accp[rp][1] = ffma2(ap[rp], bp1, accp[rp][1]);
                accp[rp][2] = ffma2(ap[rp], bp2, accp[rp][2]);
                accp[rp][3] = ffma2(ap[rp], bp3, accp[rp][3]);
            }
        }
        __syncthreads();
    }
    float4 bias4 = *(const float4*)(bdense + n0 + tx*4);
    #pragma unroll
    for (int rp = 0; rp < 4; rp++) {
        float2 c0 = unpk(accp[rp][0]);
        float2 c1 = unpk(accp[rp][1]);
        float2 c2 = unpk(accp[rp][2]);
        float2 c3 = unpk(accp[rp][3]);
        #pragma unroll
        for (int sel = 0; sel < 2; sel++) {
            int m = m0 + ty*8 + rp*2 + sel;
            if (m < ROWS) {
                int t = m >> 5, b = m & 31;
                float4 o4;
                o4.x = (sel ? c0.y : c0.x) + bias4.x;
                o4.y = (sel ? c1.y : c1.x) + bias4.y;
                o4.z = (sel ? c2.y : c2.x) + bias4.z;
                o4.w = (sel ? c3.y : c3.x) + bias4.w;
                *(float4*)(out + (size_t)(b*TD + t)*V_ + n0 + tx*4) = o4;
            }
        }
    }
}

// ---------------- fused softmax + gate + pointer scatter. grid = 1568 rows ----------------
__global__ void __launch_bounds__(256) k_finish(float* __restrict__ out,
                                                const int* __restrict__ enc_in) {
    int r = blockIdx.x;            // r = t*32 + b
    int t = r >> 5, b = r & 31;
    float* row = out + (size_t)(b*TD + t)*V_;
    int tid = threadIdx.x;

    // pass 1: online max/sum
    float m = -1e30f, s = 0.f;
    for (int v = tid*4; v < V_; v += 1024) {
        float4 x4 = *(const float4*)(row + v);
        float xs[4] = {x4.x, x4.y, x4.z, x4.w};
        #pragma unroll
        for (int i = 0; i < 4; i++) {
            float x = xs[i];
            if (x > m) { s = s*__expf(m - x) + 1.f; m = x; }
            else       { s += __expf(x - m); }
        }
    }
    __shared__ float sm[256], ss[256];
    sm[tid] = m; ss[tid] = s;
    __syncthreads();
    for (int off = 128; off; off >>= 1) {
        if (tid < off) {
            float m2 = sm[tid + off], s2 = ss[tid + off];
            float M = fmaxf(sm[tid], m2);
            ss[tid] = ss[tid]*__expf(sm[tid] - M) + s2*__expf(m2 - M);
            sm[tid] = M;
        }
        __syncthreads();
    }
    float M   = sm[0];
    float inv = 1.f / ss[0];
    float g   = g_gate[r];
    // pass 2: normalize with gate
    for (int v = tid*4; v < V_; v += 1024) {
        float4 x = *(const float4*)(row + v);
        x.x = g * __expf(x.x - M) * inv;
        x.y = g * __expf(x.y - M) * inv;
        x.z = g * __expf(x.z - M) * inv;
        x.w = g * __expf(x.w - M) * inv;
        *(float4*)(row + v) = x;
    }
    __syncthreads();
    // pass 3: pointer scatter for this row (exclusive ownership; atomics for dup tokens)
    if (tid < W_) {
        float beta = g_betas[r*W_ + tid];
        int tok = enc_in[b*W_ + tid];
        atomicAdd(row + tok, (1.f - g) * beta);
    }
}

// ---------------- launch ----------------
extern "C" void kernel_launch(void* const* d_in, const int* in_sizes, int n_in,
                              void* d_out, int out_size) {
    const int*   enc_in  = (const int*)d_in[0];
    const int*   dec_in  = (const int*)d_in[1];
    const float* emb     = (const float*)d_in[2];
    const float* Wf      = (const float*)d_in[3];
    const float* Uf      = (const float*)d_in[4];
    const float* bfv     = (const float*)d_in[5];
    const float* Wb      = (const float*)d_in[6];
    const float* Ub      = (const float*)d_in[7];
    const float* bbv     = (const float*)d_in[8];
    const float* Wd      = (const float*)d_in[9];
    const float* Ud      = (const float*)d_in[10];
    const float* bdv     = (const float*)d_in[11];
    const float* Wq      = (const float*)d_in[12];
    const float* Wdense  = (const float*)d_in[13];
    const float* bdense  = (const float*)d_in[14];
    const float* sentinel= (const float*)d_in[15];
    const float* a_bias  = (const float*)d_in[16];
    float* out = (float*)d_out;

    cudaFuncSetAttribute(k_encoder, cudaFuncAttributeMaxDynamicSharedMemorySize, 50176);
    cudaFuncSetAttribute(k_decoder, cudaFuncAttributeMaxDynamicSharedMemorySize, 126976);

    k_zero_state<<<24, 256>>>();

    k_pre<<<dim3(298, 6), 256>>>(enc_in, dec_in, emb, Wf, bfv, Wb, bbv, Wd, bdv);

    k_encoder<<<48, 256, 49920>>>(Uf, Ub);

    k_decoder<<<32, 256, 126720>>>(Wq, sentinel, a_bias, Ud, Wd);

    k_dense_gemm<<<dim3(V_/128, (ROWS + 63)/64), 256>>>(Wdense, bdense, out);

    k_finish<<<ROWS, 256>>>(out, enc_in);
}

// round 16
// speedup vs baseline: 1.6385x; 1.1387x over previous
#include <cuda_runtime.h>
#include <cuda_bf16.h>
#include <stdint.h>
#include <math.h>

typedef unsigned int u32;

#define B_   32
#define W_   50
#define H_   192
#define H4   768
#define V_   32000
#define TD   49
#define ROWS 1568   // TD * B_
#define MPAD 1664   // 13 * 128

// ---------------- device scratch (zero-initialized at module load) ----------------
__device__ float g_xf[1600*H4];         // enc fwd pre:  emb@Wf + bf   (t*32+b, n)
__device__ float g_xb[1600*H4];         // enc bwd pre
__device__ float g_xd[ROWS*H4];         // dec pre:      demb@Wd[0:192] + bd
__device__ float g_outs_f[W_*B_*H_];
__device__ float g_outs_b[W_*B_*H_];
__device__ float g_hfp[2][B_*H_];       // ping-pong h (fwd)
__device__ float g_hbp[2][B_*H_];       // ping-pong h (bwd)
__device__ float g_cf[B_*H_], g_cb[B_*H_];
__device__ float g_dh[2][B_*H_];        // decoder h ping-pong
__device__ float g_hcat[MPAD*384];      // rows padded to 1664; [h(0:192)|c_t(192:384)]; pad rows stay 0
__device__ float g_betas[TD*B_*W_];
__device__ float g_gate[TD*B_];
__device__ int   g_cnt[512];            // grid-sync counters

__device__ __forceinline__ float sigf(float x){ return 1.0f/(1.0f + expf(-x)); }

// ---------------- grid sync (global counter; CTAs guaranteed co-resident) ----------------
__device__ __forceinline__ void grid_sync(int idx, int n) {
    __syncthreads();
    if (threadIdx.x == 0) {
        __threadfence();
        atomicAdd(&g_cnt[idx], 1);
        while (*((volatile int*)&g_cnt[idx]) < n) __nanosleep(32);
        __threadfence();
    }
    __syncthreads();
}

// ---------------- init ----------------
__global__ void k_zero_state() {
    int i = blockIdx.x * 256 + threadIdx.x;
    if (i < B_*H_) {
        g_hfp[0][i] = 0.f; g_hfp[1][i] = 0.f;
        g_hbp[0][i] = 0.f; g_hbp[1][i] = 0.f;
    }
    if (i < 512) g_cnt[i] = 0;
}

// ---------------- fused pre-GEMM: [enc@Wf | enc@Wb | dec@Wd_top] ----------------
__global__ void __launch_bounds__(256) k_pre(const int* __restrict__ enc_in,
                                             const int* __restrict__ dec_in,
                                             const float* __restrict__ emb,
                                             const float* __restrict__ Wf, const float* __restrict__ bfv,
                                             const float* __restrict__ Wb, const float* __restrict__ bbv,
                                             const float* __restrict__ Wd, const float* __restrict__ bdv) {
    __shared__ float As[192*16];   // [k][r]
    __shared__ float Bs[16*128];   // [r][c]
    int row0 = blockIdx.x * 16;
    int which = (row0 < 1600) ? 0 : (row0 < 3200) ? 1 : 2;
    const int*   toks = (which == 2) ? dec_in : enc_in;
    const float* Wm   = (which == 0) ? Wf : (which == 1) ? Wb : Wd;
    const float* bias = (which == 0) ? bfv : (which == 1) ? bbv : bdv;
    float* outp = (which == 0) ? g_xf : (which == 1) ? g_xb : g_xd;
    int lr0  = row0 - which * 1600;
    int col0 = blockIdx.y * 128;
    int tid = threadIdx.x;

    for (int i = tid; i < 16*192; i += 256) {
        int r = i / 192, k = i % 192;
        int lr = lr0 + r;
        int tok = toks[(lr & 31) * W_ + (lr >> 5)];
        As[k*16 + r] = emb[tok*H_ + k];
    }
    int tx = tid & 31, ty = tid >> 5;
    float a0c[4] = {0,0,0,0}, a1c[4] = {0,0,0,0};
    for (int k0 = 0; k0 < 192; k0 += 16) {
        __syncthreads();
        for (int i = tid; i < 16*128; i += 256) {
            int r = i >> 7, c = i & 127;
            Bs[i] = Wm[(size_t)(k0 + r)*H4 + col0 + c];
        }
        __syncthreads();
        #pragma unroll
        for (int kk = 0; kk < 16; kk++) {
            float a0 = As[(k0+kk)*16 + ty];
            float a1 = As[(k0+kk)*16 + ty + 8];
            float4 w = *(float4*)&Bs[kk*128 + tx*4];
            a0c[0] = fmaf(a0,w.x,a0c[0]); a0c[1] = fmaf(a0,w.y,a0c[1]);
            a0c[2] = fmaf(a0,w.z,a0c[2]); a0c[3] = fmaf(a0,w.w,a0c[3]);
            a1c[0] = fmaf(a1,w.x,a1c[0]); a1c[1] = fmaf(a1,w.y,a1c[1]);
            a1c[2] = fmaf(a1,w.z,a1c[2]); a1c[3] = fmaf(a1,w.w,a1c[3]);
        }
    }
    float4 b4 = *(const float4*)(bias + col0 + tx*4);
    float4 o;
    o.x = a0c[0]+b4.x; o.y = a0c[1]+b4.y; o.z = a0c[2]+b4.z; o.w = a0c[3]+b4.w;
    *(float4*)(outp + (size_t)(lr0 + ty)*H4 + col0 + tx*4) = o;
    o.x = a1c[0]+b4.x; o.y = a1c[1]+b4.y; o.z = a1c[2]+b4.z; o.w = a1c[3]+b4.w;
    *(float4*)(outp + (size_t)(lr0 + ty + 8)*H4 + col0 + tx*4) = o;
}

// ---------------- persistent encoder: 48 CTAs (24/dir), weight-stationary ----------------
__global__ void __launch_bounds__(256) k_encoder(const float* __restrict__ Uf,
                                                 const float* __restrict__ Ub) {
    extern __shared__ float esm[];
    float* ws = esm;           // 192 * 32
    float* hs = esm + 6144;    // 192 * 33

    int cta = blockIdx.x;
    int dir = cta / 24;
    int nc  = cta % 24;
    const float* U    = dir ? Ub   : Uf;
    const float* xpre = dir ? g_xb : g_xf;
    float* outs = dir ? g_outs_b : g_outs_f;
    float* cfin = dir ? g_cb : g_cf;
    float* hping[2];
    hping[0] = dir ? g_hbp[0] : g_hfp[0];
    hping[1] = dir ? g_hbp[1] : g_hfp[1];

    int tid = threadIdx.x;
    int jl  = tid >> 5;
    int b   = tid & 31;
    int jg  = nc*8 + jl;

    for (int i = tid; i < 192*32; i += 256) {
        int k = i >> 5, col = i & 31;
        int g = col >> 3, j = col & 7;
        ws[i] = U[k*H4 + g*H_ + nc*8 + j];
    }

    float c_reg = 0.f;
    for (int s = 0; s < W_; s++) {
        int t = dir ? (W_ - 1 - s) : s;
        const float* hin = hping[s & 1];
        for (int i = tid; i < 192*32; i += 256) {
            int bb = i / 192, k = i % 192;
            hs[k*33 + bb] = __ldcg(&hin[i]);
        }
        __syncthreads();

        const float* xr = xpre + (size_t)(t*B_ + b)*H4;
        float acc0 = xr[0*H_ + jg];
        float acc1 = xr[1*H_ + jg];
        float acc2 = xr[2*H_ + jg];
        float acc3 = xr[3*H_ + jg];
        #pragma unroll 8
        for (int k = 0; k < H_; k++) {
            float hv = hs[k*33 + b];
            acc0 = fmaf(hv, ws[k*32 +      jl], acc0);
            acc1 = fmaf(hv, ws[k*32 +  8 + jl], acc1);
            acc2 = fmaf(hv, ws[k*32 + 16 + jl], acc2);
            acc3 = fmaf(hv, ws[k*32 + 24 + jl], acc3);
        }
        float cn = sigf(acc1)*c_reg + sigf(acc0)*tanhf(acc2);
        float hn = sigf(acc3)*tanhf(cn);
        c_reg = cn;
        hping[(s & 1) ^ 1][b*H_ + jg] = hn;
        outs[(t*B_ + b)*H_ + jg] = hn;

        if (s < W_ - 1) grid_sync(dir*64 + s, 24);
    }
    cfin[b*H_ + jg] = c_reg;
}

// ---------------- persistent decoder: 32 CTAs ----------------
__global__ void __launch_bounds__(256) k_decoder(const float* __restrict__ Wq,
                                                 const float* __restrict__ sentinel,
                                                 const float* __restrict__ a_bias,
                                                 const float* __restrict__ Ud,
                                                 const float* __restrict__ Wd) {
    extern __shared__ float dsm[];
    float* fatt = dsm;                  // 51*192
    float* ws   = dsm + 9792;           // 384*24
    float* hct  = dsm + 19008;          // 384*33
    __shared__ float hsh[192];
    __shared__ float q[192];
    __shared__ float sc[64];

    int cta = blockIdx.x;
    int tid = threadIdx.x;

    for (int i = tid; i < W_*H_; i += 256) {
        int w = i / H_, k = i % H_;
        fatt[i] = g_outs_f[(w*B_ + cta)*H_ + k] + g_outs_b[(w*B_ + cta)*H_ + k];
    }
    if (tid < H_) fatt[W_*H_ + tid] = sentinel[tid];

    for (int i = tid; i < 384*24; i += 256) {
        int k = i / 24, col = i % 24;
        int g = col / 6, j = col % 6;
        int n = g*H_ + cta*6 + j;
        ws[i] = (k < 192) ? Ud[k*H4 + n] : Wd[(size_t)k*H4 + n];
    }

    if (tid < H_)
        g_dh[0][cta*H_ + tid] = g_hfp[0][cta*H_ + tid] + g_hbp[0][cta*H_ + tid];
    int jl = tid >> 5;
    int b  = tid & 31;
    int jg = cta*6 + jl;
    float c_reg = 0.f;
    if (jl < 6) c_reg = g_cf[b*H_ + jg] + g_cb[b*H_ + jg];

    grid_sync(128, 32);

    for (int t = 0; t < TD; t++) {
        const float* hin = g_dh[t & 1];

        if (tid < H_) hsh[tid] = __ldcg(&hin[cta*H_ + tid]);
        __syncthreads();
        if (tid < H_) {
            float a = 0.f;
            #pragma unroll 8
            for (int k = 0; k < H_; k++) a = fmaf(hsh[k], Wq[k*H_ + tid], a);
            q[tid] = a;
        }
        __syncthreads();
        int warp = tid >> 5, lane = tid & 31;
        for (int j = warp; j < 51; j += 8) {
            float s = 0.f;
            for (int k = lane; k < H_; k += 32) s += tanhf(fatt[j*H_ + k] * q[k]);
            #pragma unroll
            for (int off = 16; off; off >>= 1) s += __shfl_xor_sync(0xffffffffu, s, off);
            if (lane == 0) sc[j] = s + a_bias[t*(W_+1) + j];
        }
        __syncthreads();
        if (tid < 32) {
            float v0 = sc[tid];
            float v1 = (tid + 32 < 51) ? sc[tid + 32] : -1e30f;
            float m = fmaxf(v0, v1);
            #pragma unroll
            for (int off = 16; off; off >>= 1) m = fmaxf(m, __shfl_xor_sync(0xffffffffu, m, off));
            float e0 = expf(v0 - m);
            float e1 = (tid + 32 < 51) ? expf(v1 - m) : 0.f;
            float s = e0 + e1;
            #pragma unroll
            for (int off = 16; off; off >>= 1) s += __shfl_xor_sync(0xffffffffu, s, off);
            float inv = 1.f / s;
            sc[tid] = e0 * inv;
            if (tid + 32 < 51) sc[tid + 32] = e1 * inv;
        }
        __syncthreads();
        if (tid < W_) g_betas[(t*B_ + cta)*W_ + tid] = sc[tid];
        if (tid == W_) g_gate[t*B_ + cta] = sc[W_];
        if (tid < H_) {
            float a = 0.f;
            #pragma unroll
            for (int w = 0; w < W_; w++) a = fmaf(fatt[w*H_ + tid], sc[w], a);
            g_hcat[(size_t)(t*B_ + cta)*384 + 192 + tid] = a;
        }
        grid_sync(130 + 2*t, 32);

        for (int i = tid; i < 192*32; i += 256) {
            int bb = i / 192, k = i % 192;
            hct[k*33 + bb]         = __ldcg(&hin[i]);
            hct[(192 + k)*33 + bb] = __ldcg(&g_hcat[(size_t)(t*B_ + bb)*384 + 192 + k]);
        }
        __syncthreads();
        if (jl < 6) {
            const float* xr = g_xd + (size_t)(t*B_ + b)*H4;
            float acc0 = xr[0*H_ + jg];
            float acc1 = xr[1*H_ + jg];
            float acc2 = xr[2*H_ + jg];
            float acc3 = xr[3*H_ + jg];
            #pragma unroll 8
            for (int k = 0; k < 384; k++) {
                float hv = hct[k*33 + b];
                acc0 = fmaf(hv, ws[k*24 +      jl], acc0);
                acc1 = fmaf(hv, ws[k*24 +  6 + jl], acc1);
                acc2 = fmaf(hv, ws[k*24 + 12 + jl], acc2);
                acc3 = fmaf(hv, ws[k*24 + 18 + jl], acc3);
            }
            float cn = sigf(acc1)*c_reg + sigf(acc0)*tanhf(acc2);
            float hn = sigf(acc3)*tanhf(cn);
            c_reg = cn;
            g_dh[(t & 1) ^ 1][b*H_ + jg] = hn;
            g_hcat[(size_t)(t*B_ + b)*384 + jg] = hn;
        }
        if (t < TD - 1) grid_sync(131 + 2*t, 32);
    }
}

// ---------------- tensor-core GEMM: out = hcat[1664x384] @ Wdense[384x32000] + bias ----------------
// bf16 hi/lo 3-term split, mma.m16n8k16. CTA tile 128x128, Kchunk 64, 8 warps (4m x 2n), warp 32x64.
#define ASTR 72    // A smem row stride (bf16)
#define BSTR 136   // B smem row stride (bf16)

__device__ __forceinline__ void ldmx4(u32* r, u32 addr) {
    asm volatile("ldmatrix.sync.aligned.m8n8.x4.shared.b16 {%0,%1,%2,%3}, [%4];"
                 : "=r"(r[0]), "=r"(r[1]), "=r"(r[2]), "=r"(r[3]) : "r"(addr));
}
__device__ __forceinline__ void ldmx4t(u32* r, u32 addr) {
    asm volatile("ldmatrix.sync.aligned.m8n8.x4.trans.shared.b16 {%0,%1,%2,%3}, [%4];"
                 : "=r"(r[0]), "=r"(r[1]), "=r"(r[2]), "=r"(r[3]) : "r"(addr));
}
__device__ __forceinline__ void mma16816(float* d, const u32* a, u32 b0, u32 b1) {
    asm volatile("mma.sync.aligned.m16n8k16.row.col.f32.bf16.bf16.f32 "
                 "{%0,%1,%2,%3},{%4,%5,%6,%7},{%8,%9},{%0,%1,%2,%3};"
                 : "+f"(d[0]), "+f"(d[1]), "+f"(d[2]), "+f"(d[3])
                 : "r"(a[0]), "r"(a[1]), "r"(a[2]), "r"(a[3]), "r"(b0), "r"(b1));
}
__device__ __forceinline__ void split2(float x, float y, u32& hi, u32& lo) {
    __nv_bfloat162 h2 = __floats2bfloat162_rn(x, y);
    float hx = __bfloat162float(h2.x);
    float hy = __bfloat162float(h2.y);
    __nv_bfloat162 l2 = __floats2bfloat162_rn(x - hx, y - hy);
    hi = *(u32*)&h2; lo = *(u32*)&l2;
}

__global__ void __launch_bounds__(256, 2) k_tc_gemm(const float* __restrict__ Wdense,
                                                    const float* __restrict__ bdense,
                                                    float* __restrict__ out) {
    extern __shared__ unsigned char gsm[];
    __nv_bfloat16* AsHi = (__nv_bfloat16*)gsm;                 // 128 x 72
    __nv_bfloat16* AsLo = AsHi + 128*ASTR;
    __nv_bfloat16* BsHi = AsLo + 128*ASTR;                     // 64 x 136
    __nv_bfloat16* BsLo = BsHi + 64*BSTR;

    u32 sAhi = (u32)__cvta_generic_to_shared(AsHi);
    u32 sAlo = (u32)__cvta_generic_to_shared(AsLo);
    u32 sBhi = (u32)__cvta_generic_to_shared(BsHi);
    u32 sBlo = (u32)__cvta_generic_to_shared(BsLo);

    int n0 = blockIdx.x * 128;
    int m0 = blockIdx.y * 128;
    int tid  = threadIdx.x;
    int lane = tid & 31;
    int wid  = tid >> 5;
    int wm = wid & 3;         // 0..3 -> 32 rows each
    int wn = wid >> 2;        // 0..1 -> 64 cols each
    int g   = lane >> 2;
    int tig = lane & 3;

    u32 aRow = (u32)(wm*32 + (lane & 15));
    u32 aColOff = (u32)((lane >> 4) * 8);
    u32 bK = (u32)(lane & 15);
    u32 bN = (u32)(wn*64 + (lane >> 4) * 8);

    float acc[64];
    #pragma unroll
    for (int i = 0; i < 64; i++) acc[i] = 0.f;

    for (int k0 = 0; k0 < 384; k0 += 64) {
        // ---- fill A tile (128 x 64) with hi/lo split ----
        #pragma unroll
        for (int i = 0; i < 8; i++) {
            int idx4 = tid + i*256;          // float4 index, 0..2047
            int r = idx4 >> 4;               // /16
            int c = (idx4 & 15) * 4;
            float4 a4 = *(const float4*)(g_hcat + (size_t)(m0 + r)*384 + k0 + c);
            u32 h0, l0, h1, l1;
            split2(a4.x, a4.y, h0, l0);
            split2(a4.z, a4.w, h1, l1);
            int so = r*ASTR + c;
            *(u32*)(AsHi + so)     = h0;
            *(u32*)(AsHi + so + 2) = h1;
            *(u32*)(AsLo + so)     = l0;
            *(u32*)(AsLo + so + 2) = l1;
        }
        // ---- fill B tile (64 x 128) with hi/lo split ----
        #pragma unroll
        for (int i = 0; i < 8; i++) {
            int idx4 = tid + i*256;
            int kr = idx4 >> 5;              // /32
            int nc = (idx4 & 31) * 4;
            float4 b4 = *(const float4*)(Wdense + (size_t)(k0 + kr)*V_ + n0 + nc);
            u32 h0, l0, h1, l1;
            split2(b4.x, b4.y, h0, l0);
            split2(b4.z, b4.w, h1, l1);
            int so = kr*BSTR + nc;
            *(u32*)(BsHi + so)     = h0;
            *(u32*)(BsHi + so + 2) = h1;
            *(u32*)(BsLo + so)     = l0;
            *(u32*)(BsLo + so + 2) = l1;
        }
        __syncthreads();

        // ---- compute: 4 k16 steps ----
        #pragma unroll
        for (int ks = 0; ks < 4; ks++) {
            u32 ah[2][4], al[2][4];
            #pragma unroll
            for (int mf = 0; mf < 2; mf++) {
                u32 off = ((aRow + mf*16)*ASTR + ks*16 + aColOff) * 2;
                ldmx4(ah[mf], sAhi + off);
                ldmx4(al[mf], sAlo + off);
            }
            #pragma unroll
            for (int nf2 = 0; nf2 < 4; nf2++) {
                u32 boff = ((ks*16 + bK)*BSTR + bN + nf2*16) * 2;
                u32 bh[4], bl[4];
                ldmx4t(bh, sBhi + boff);
                ldmx4t(bl, sBlo + boff);
                #pragma unroll
                for (int mf = 0; mf < 2; mf++) {
                    float* d0 = &acc[(mf*8 + nf2*2)*4];
                    float* d1 = &acc[(mf*8 + nf2*2 + 1)*4];
                    mma16816(d0, ah[mf], bh[0], bh[1]);
                    mma16816(d1, ah[mf], bh[2], bh[3]);
                    mma16816(d0, ah[mf], bl[0], bl[1]);
                    mma16816(d1, ah[mf], bl[2], bl[3]);
                    mma16816(d0, al[mf], bh[0], bh[1]);
                    mma16816(d1, al[mf], bh[2], bh[3]);
                }
            }
        }
        __syncthreads();
    }

    // ---- epilogue: bias + permuted-row store ----
    #pragma unroll
    for (int mf = 0; mf < 2; mf++) {
        #pragma unroll
        for (int nf = 0; nf < 8; nf++) {
            int col = n0 + wn*64 + nf*8 + tig*2;
            float b0v = bdense[col], b1v = bdense[col+1];
            float* ap = &acc[(mf*8 + nf)*4];
            int mA = m0 + wm*32 + mf*16 + g;
            if (mA < ROWS) {
                size_t ro = (size_t)((mA & 31)*TD + (mA >> 5)) * V_;
                float2 v = make_float2(ap[0] + b0v, ap[1] + b1v);
                *(float2*)(out + ro + col) = v;
            }
            int mB = mA + 8;
            if (mB < ROWS) {
                size_t ro = (size_t)((mB & 31)*TD + (mB >> 5)) * V_;
                float2 v = make_float2(ap[2] + b0v, ap[3] + b1v);
                *(float2*)(out + ro + col) = v;
            }
        }
    }
}

// ---------------- fused softmax + gate + pointer scatter. grid = 1568 rows ----------------
__global__ void __launch_bounds__(256) k_finish(float* __restrict__ out,
                                                const int* __restrict__ enc_in) {
    int r = blockIdx.x;            // r = t*32 + b
    int t = r >> 5, b = r & 31;
    float* row = out + (size_t)(b*TD + t)*V_;
    int tid = threadIdx.x;

    float m = -1e30f, s = 0.f;
    for (int v = tid*4; v < V_; v += 1024) {
        float4 x4 = *(const float4*)(row + v);
        float xs[4] = {x4.x, x4.y, x4.z, x4.w};
        #pragma unroll
        for (int i = 0; i < 4; i++) {
            float x = xs[i];
            if (x > m) { s = s*__expf(m - x) + 1.f; m = x; }
            else       { s += __expf(x - m); }
        }
    }
    __shared__ float sm[256], ss[256];
    sm[tid] = m; ss[tid] = s;
    __syncthreads();
    for (int off = 128; off; off >>= 1) {
        if (tid < off) {
            float m2 = sm[tid + off], s2 = ss[tid + off];
            float M = fmaxf(sm[tid], m2);
            ss[tid] = ss[tid]*__expf(sm[tid] - M) + s2*__expf(m2 - M);
            sm[tid] = M;
        }
        __syncthreads();
    }
    float M   = sm[0];
    float inv = 1.f / ss[0];
    float g   = g_gate[r];
    for (int v = tid*4; v < V_; v += 1024) {
        float4 x = *(const float4*)(row + v);
        x.x = g * __expf(x.x - M) * inv;
        x.y = g * __expf(x.y - M) * inv;
        x.z = g * __expf(x.z - M) * inv;
        x.w = g * __expf(x.w - M) * inv;
        *(float4*)(row + v) = x;
    }
    __syncthreads();
    if (tid < W_) {
        float beta = g_betas[r*W_ + tid];
        int tok = enc_in[b*W_ + tid];
        atomicAdd(row + tok, (1.f - g) * beta);
    }
}

// ---------------- launch ----------------
extern "C" void kernel_launch(void* const* d_in, const int* in_sizes, int n_in,
                              void* d_out, int out_size) {
    const int*   enc_in  = (const int*)d_in[0];
    const int*   dec_in  = (const int*)d_in[1];
    const float* emb     = (const float*)d_in[2];
    const float* Wf      = (const float*)d_in[3];
    const float* Uf      = (const float*)d_in[4];
    const float* bfv     = (const float*)d_in[5];
    const float* Wb      = (const float*)d_in[6];
    const float* Ub      = (const float*)d_in[7];
    const float* bbv     = (const float*)d_in[8];
    const float* Wd      = (const float*)d_in[9];
    const float* Ud      = (const float*)d_in[10];
    const float* bdv     = (const float*)d_in[11];
    const float* Wq      = (const float*)d_in[12];
    const float* Wdense  = (const float*)d_in[13];
    const float* bdense  = (const float*)d_in[14];
    const float* sentinel= (const float*)d_in[15];
    const float* a_bias  = (const float*)d_in[16];
    float* out = (float*)d_out;

    cudaFuncSetAttribute(k_encoder, cudaFuncAttributeMaxDynamicSharedMemorySize, 50176);
    cudaFuncSetAttribute(k_decoder, cudaFuncAttributeMaxDynamicSharedMemorySize, 126976);
    cudaFuncSetAttribute(k_tc_gemm, cudaFuncAttributeMaxDynamicSharedMemorySize, 71680);

    k_zero_state<<<24, 256>>>();

    k_pre<<<dim3(298, 6), 256>>>(enc_in, dec_in, emb, Wf, bfv, Wb, bbv, Wd, bdv);

    k_encoder<<<48, 256, 49920>>>(Uf, Ub);

    k_decoder<<<32, 256, 126720>>>(Wq, sentinel, a_bias, Ud, Wd);

    k_tc_gemm<<<dim3(V_/128, MPAD/128), 256, 71680>>>(Wdense, bdense, out);

    k_finish<<<ROWS, 256>>>(out, enc_in);
}